// round 14
// baseline (speedup 1.0000x reference)
#include <cuda_runtime.h>

// Problem constants
#define BC        20      // B*C
#define HLEN      200     // his_length
#define DK        20
#define NROWS     4000    // BC*HLEN
#define ROW_ELEMS 8000    // D_INNER(400) * DK(20)
#define CTX_ELEMS (NROWS*DK)        // 80000
#define ATTN_OFF  CTX_ELEMS

// Projected q,k,v,c in TRANSPOSED layout: [bc][d][h] -> (bc*20+d)*200+h
__device__ float g_qT[CTX_ELEMS];
__device__ float g_kT[CTX_ELEMS];
__device__ float g_vT[CTX_ELEMS];
__device__ float g_cT[CTX_ELEMS];

// Producer-consumer sync (zero at first launch; the 20th attn block of each
// bc resets both counters, so every graph replay starts from zero).
__device__ int g_cnt[BC];
__device__ int g_done[BC];

#define PROJ_BLOCKS   12000          // bc*600 + a*200 + h   (grouped by bc)
#define ATTN_PER_BC   20
#define TOTAL_BLOCKS  (PROJ_BLOCKS + BC * ATTN_PER_BC)   // 12400

// Dynamic smem union (floats):
//   proj: Ws @0 (400), red(float4) @400 (800 floats)          -> 1200
//   attn: partials @0 (200), ctxp @200 (200*21=4200), rss @4400 (10) -> 4410
#define SM_PART  0
#define SM_CTXP  200
#define SM_RSS   4400
#define SMEM_FLOATS 4410
#define SMEM_BYTES  (SMEM_FLOATS * 4)

__global__ __launch_bounds__(200, 8) void mega_kernel(
    const float* __restrict__ Q, const float* __restrict__ K,
    const float* __restrict__ V, const float* __restrict__ cdd,
    const float* __restrict__ W, const float* __restrict__ bp,
    const float* __restrict__ W1, const float* __restrict__ b1p,
    float* __restrict__ out)
{
    extern __shared__ float sm[];
    const int bid = blockIdx.x;
    const int t   = threadIdx.x;    // 0..199

    if (bid < PROJ_BLOCKS) {
        // ================= PROJ block (exact R5 body, 200 threads) ========
        const int bc = bid / 600;
        const int w  = bid - bc * 600;
        const int a  = w / HLEN;          // tensor 0..2
        const int h  = w - a * HLEN;      // row within bc
        const int r  = bc * HLEN + h;

        float*  Ws  = sm;                        // 400
        float4* red = (float4*)(sm + 400);       // 200 float4

        Ws[t]       = W[t];
        Ws[t + 200] = W[t + 200];
        __syncthreads();

        const float bias = __ldg(bp);
        const size_t base = (size_t)r * ROW_ELEMS;
        const float* src = (a == 0) ? (Q + base) : (a == 1) ? (K + base) : (V + base);
        float*       dst = (a == 0) ? g_qT : (a == 1) ? g_kT : g_vT;

        const float4* p = (const float4*)src;
        float a0 = 0.f, a1 = 0.f, a2 = 0.f, a3 = 0.f;
        #pragma unroll
        for (int j = 0; j < 10; j++) {
            const int i4 = t + 200 * j;
            const float4 v4 = p[i4];
            const float wv = Ws[(i4 * 4) / 20];   // same n for all 4 lanes
            a0 += v4.x * wv;
            a1 += v4.y * wv;
            a2 += v4.z * wv;
            a3 += v4.w * wv;
        }
        red[t] = make_float4(a0, a1, a2, a3);
        __syncthreads();

        if (t < 20) {
            const int e  = t & 3;
            const int st = t >> 2;
            float s = bias;
            #pragma unroll 8
            for (int tp = st; tp < 200; tp += 5)
                s += ((const float*)&red[tp])[e];
            dst[(bc * DK + t) * HLEN + h] = s;
        }
        if (a == 2 && t < 20) {
            const float b1 = __ldg(b1p);
            const float* cb = cdd + (size_t)r * 400;
            float s = b1;
            #pragma unroll
            for (int n = 0; n < 20; n++)
                s += cb[n * 20 + t] * __ldg(W1 + n);
            g_cT[(bc * DK + t) * HLEN + h] = s;
        }

        // Release: writes visible, then signal.
        __threadfence();
        __syncthreads();
        if (t == 0) atomicAdd(&g_cnt[bc], 1);

    } else {
        // ================= ATTN block (consumer, 200 threads) =============
        const int ab = bid - PROJ_BLOCKS;
        const int bc = ab / ATTN_PER_BC;
        const int mt = ab - bc * ATTN_PER_BC;     // 0..19
        const int m0 = mt * 10;

        float* partials = sm + SM_PART;  // 200
        float* ctxp     = sm + SM_CTXP;  // [t][d] stride 21
        float* rss      = sm + SM_RSS;   // 10

        // Acquire: wait for all 600 proj blocks of this bc.
        if (t == 0) {
            while (*(volatile int*)&g_cnt[bc] < 600) {}
            __threadfence();
        }
        __syncthreads();

        const int m   = t / 20;          // local row 0..9
        const int ng  = t - 20 * m;      // 0..19
        const int col = m0 + m;          // global row h
        const int tb  = bc * DK * HLEN;

        // ---- scores: s[j] over n = ng + 20*j (k/c tiles are L1-hot) ----
        float s[10];
        #pragma unroll
        for (int j = 0; j < 10; j++) s[j] = 0.f;

        #pragma unroll 5
        for (int d = 0; d < DK; d++) {
            const float xv = g_qT[tb + d * HLEN + col];          // broadcast
            const float* y = g_kT + tb + d * HLEN + ng;
            #pragma unroll
            for (int j = 0; j < 10; j++)
                s[j] += xv * y[20 * j];
        }
        #pragma unroll 5
        for (int d = 0; d < DK; d++) {
            const float xv = g_kT[tb + d * HLEN + col];          // broadcast
            const float* y = g_cT + tb + d * HLEN + ng;
            #pragma unroll
            for (int j = 0; j < 10; j++)
                s[j] += xv * y[20 * j];
        }

        const float isd = 0.22360679774997896f;   // 1/sqrt(20)
        float e[10];
        float esum = 0.f;
        #pragma unroll
        for (int j = 0; j < 10; j++) {
            e[j] = __expf(s[j] * isd);
            esum += e[j];
        }
        partials[t] = esum;
        __syncthreads();

        if (t < 10) {
            float ssum = 1e-8f;
            #pragma unroll
            for (int q = 0; q < 20; q++)
                ssum += partials[t * 20 + q];
            rss[t] = 1.f / ssum;
        }
        __syncthreads();

        // ---- normalized attn writes straight from registers ----
        const float rs = rss[m];
        float* attn = out + ATTN_OFF + (size_t)(bc * HLEN + col) * HLEN;
        #pragma unroll
        for (int j = 0; j < 10; j++)
            attn[ng + 20 * j] = e[j] * rs;

        // ---- context partials (unnormalized; v tile L1-hot) ----
        #pragma unroll 5
        for (int d = 0; d < DK; d++) {
            const float* v = g_vT + tb + d * HLEN + ng;
            float c = 0.f;
            #pragma unroll
            for (int j = 0; j < 10; j++)
                c += e[j] * v[20 * j];
            ctxp[t * 21 + d] = c;
        }
        __syncthreads();

        // ---- context reduce + write (200 outputs, 20 partials each) ----
        {
            const int mm = t / DK, dd = t - DK * mm;
            float c = 0.f;
            #pragma unroll
            for (int q = 0; q < 20; q++)
                c += ctxp[(mm * 20 + q) * 21 + dd];
            out[(bc * HLEN + m0 + mm) * DK + dd] = c * rss[mm];
        }

        // ---- reset counters for the next graph replay ----
        __syncthreads();
        if (t == 0) {
            const int v = atomicAdd(&g_done[bc], 1);
            if (v == ATTN_PER_BC - 1) {
                g_cnt[bc]  = 0;
                g_done[bc] = 0;
                __threadfence();
            }
        }
    }
}

extern "C" void kernel_launch(void* const* d_in, const int* in_sizes, int n_in,
                              void* d_out, int out_size)
{
    const float* Q   = (const float*)d_in[0];
    const float* K   = (const float*)d_in[1];
    const float* V   = (const float*)d_in[2];
    const float* cdd = (const float*)d_in[3];
    const float* W   = (const float*)d_in[4];
    const float* b   = (const float*)d_in[5];
    const float* W1  = (const float*)d_in[6];
    const float* b1  = (const float*)d_in[7];

    mega_kernel<<<TOTAL_BLOCKS, 200, SMEM_BYTES>>>(
        Q, K, V, cdd, W, b, W1, b1, (float*)d_out);
}

// round 15
// speedup vs baseline: 2.1775x; 2.1775x over previous
#include <cuda_runtime.h>

// Problem constants
#define BC        20      // B*C
#define HLEN      200     // his_length
#define DK        20
#define NROWS     4000    // BC*HLEN
#define ROW_ELEMS 8000    // D_INNER(400) * DK(20)
#define CTX_ELEMS (NROWS*DK)        // 80000
#define ATTN_OFF  CTX_ELEMS

// Projected q,k,v,c in TRANSPOSED layout: [bc][d][h] -> (bc*20+d)*200+h
__device__ float g_qT[CTX_ELEMS];
__device__ float g_kT[CTX_ELEMS];
__device__ float g_vT[CTX_ELEMS];
__device__ float g_cT[CTX_ELEMS];

// Per-(bc, ntile) partials, unique writer per slot -> no atomics, no zeroing.
// g_ctxp[(bc*4+nt)*200*20 + m*20 + d], g_sump[(bc*4+nt)*200 + m]
__device__ float g_ctxp[BC * 4 * HLEN * DK];
__device__ float g_sump[BC * 4 * HLEN];

// ---------------------------------------------------------------------------
// Kernel 1: projections (R5 body, proven 82.8% DRAM; + __ldcs streaming hint).
// grid = (row 0..3999, tensor 0..2); 200 threads.
// ---------------------------------------------------------------------------
__global__ __launch_bounds__(200) void proj_kernel(
    const float* __restrict__ Q, const float* __restrict__ K,
    const float* __restrict__ V, const float* __restrict__ cdd,
    const float* __restrict__ W, const float* __restrict__ bp,
    const float* __restrict__ W1, const float* __restrict__ b1p)
{
    __shared__ float Ws[400];
    __shared__ float4 red[200];

    const int r = blockIdx.x;      // row 0..3999
    const int a = blockIdx.y;      // tensor 0..2
    const int t = threadIdx.x;     // 0..199
    const int bc = r / HLEN;
    const int h  = r - bc * HLEN;

    Ws[t]       = W[t];
    Ws[t + 200] = W[t + 200];
    __syncthreads();

    const float bias = __ldg(bp);
    const size_t base = (size_t)r * ROW_ELEMS;

    const float* src = (a == 0) ? (Q + base) : (a == 1) ? (K + base) : (V + base);
    float*       dst = (a == 0) ? g_qT : (a == 1) ? g_kT : g_vT;

    const float4* p = (const float4*)src;
    float a0 = 0.f, a1 = 0.f, a2 = 0.f, a3 = 0.f;
    #pragma unroll
    for (int j = 0; j < 10; j++) {
        const int i4 = t + 200 * j;
        const float4 v4 = __ldcs(&p[i4]);      // evict-first streaming
        const float wv = Ws[(i4 * 4) / 20];    // same n for all 4 lanes
        a0 += v4.x * wv;
        a1 += v4.y * wv;
        a2 += v4.z * wv;
        a3 += v4.w * wv;
    }
    red[t] = make_float4(a0, a1, a2, a3);
    __syncthreads();

    if (t < 20) {
        const int e  = t & 3;
        const int st = t >> 2;
        float s = bias;
        #pragma unroll 8
        for (int tp = st; tp < 200; tp += 5)
            s += ((const float*)&red[tp])[e];
        dst[(bc * DK + t) * HLEN + h] = s;
    }

    if (a == 2 && t < 20) {
        const float b1 = __ldg(b1p);
        const float* cb = cdd + (size_t)r * 400;
        float s = b1;
        #pragma unroll
        for (int n = 0; n < 20; n++)
            s += cb[n * 20 + t] * __ldg(W1 + n);
        g_cT[(bc * DK + t) * HLEN + h] = s;
    }
}

// ---------------------------------------------------------------------------
// Kernel 2: scores + exp + PER-TILE partial rowsums / partial E*V context.
// grid (bc=20, mtile=4, ntile=4), 256 threads (16x16), 4x4 register tile.
// smem (floats): xs 40*64=2560 @0, ys 2560 @2560, vs 64*21=1344 @5120.
// After the GEMM, xs/ys are dead: cbuf(64*4*16=4096)@0, sbuf(64*16=1024)@4096
// overlay them for the cross-tx reductions.
// ---------------------------------------------------------------------------
#define VS_STR 21
#define SC_SMEM (2560 + 2560 + 64 * VS_STR)

__global__ __launch_bounds__(256) void score_kernel(float* __restrict__ out)
{
    __shared__ float sm[SC_SMEM];
    float* xs   = sm;             // [d][m] d<40
    float* ys   = sm + 2560;      // [d][n] d<40
    float* vs   = sm + 5120;      // [n][d] stride 21
    float* cbuf = sm;             // overlay: [m][dd][tx] 64*4*16
    float* sbuf = sm + 4096;      // overlay: [m][tx]     64*16

    const int bc = blockIdx.x;
    const int m0 = blockIdx.y * 64;
    const int n0 = blockIdx.z * 64;
    const int nt = blockIdx.z;
    const int t  = threadIdx.x;

    // ---- stage xs, ys (coalesced LDG from transposed gmem) ----
    for (int i = t; i < 2560; i += 256) {
        const int d = i >> 6;
        const int m = i & 63;
        const int hm = m0 + m;
        const int hn = n0 + m;
        float xv = 0.f, yv = 0.f;
        if (d < 20) {
            const int rowb = (bc * DK + d) * HLEN;
            if (hm < HLEN) xv = g_qT[rowb + hm];
            if (hn < HLEN) yv = g_kT[rowb + hn];
        } else {
            const int rowb = (bc * DK + d - 20) * HLEN;
            if (hm < HLEN) xv = g_kT[rowb + hm];
            if (hn < HLEN) yv = g_cT[rowb + hn];
        }
        xs[i] = xv;
        ys[i] = yv;
    }
    // ---- stage vs[n][d] (coalesced over n) ----
    for (int i = t; i < 64 * DK; i += 256) {
        const int d = i >> 6;
        const int n = i & 63;
        vs[n * VS_STR + d] = (n0 + n < HLEN)
            ? g_vT[(bc * DK + d) * HLEN + n0 + n] : 0.f;
    }
    __syncthreads();

    const int tx = t & 15;           // n-subtile
    const int ty = t >> 4;           // m-subtile
    float acc[4][4];
    #pragma unroll
    for (int i = 0; i < 4; i++)
        #pragma unroll
        for (int j = 0; j < 4; j++)
            acc[i][j] = 0.f;

    #pragma unroll
    for (int d = 0; d < 40; d++) {
        const float4 xv = *(const float4*)&xs[d * 64 + ty * 4];
        const float4 yv = *(const float4*)&ys[d * 64 + tx * 4];
        const float xa[4] = { xv.x, xv.y, xv.z, xv.w };
        const float ya[4] = { yv.x, yv.y, yv.z, yv.w };
        #pragma unroll
        for (int i = 0; i < 4; i++)
            #pragma unroll
            for (int j = 0; j < 4; j++)
                acc[i][j] += xa[i] * ya[j];
    }

    // ---- exp (guarded) + unnormalized E writes + per-thread row partials --
    const float isd = 0.22360679774997896f;   // 1/sqrt(20)
    float e[4][4];
    float rsum[4];
    float* E = out + ATTN_OFF;
    #pragma unroll
    for (int i = 0; i < 4; i++) {
        const int m = m0 + ty * 4 + i;
        rsum[i] = 0.f;
        #pragma unroll
        for (int j = 0; j < 4; j++) {
            const int n = n0 + tx * 4 + j;
            const bool valid = (m < HLEN) && (n < HLEN);
            e[i][j] = valid ? __expf(acc[i][j] * isd) : 0.f;
            rsum[i] += e[i][j];
            if (valid) E[(size_t)(bc * HLEN + m) * HLEN + n] = e[i][j];
        }
    }
    __syncthreads();    // xs/ys dead -> overlay cbuf/sbuf

    // ---- rowsum partials: reduce over tx ----
    #pragma unroll
    for (int i = 0; i < 4; i++)
        sbuf[(ty * 4 + i) * 16 + tx] = rsum[i];

    // ---- context partials, 5 chunks of 4 dims ----
    #pragma unroll 1
    for (int c = 0; c < 5; c++) {
        #pragma unroll
        for (int i = 0; i < 4; i++) {
            #pragma unroll
            for (int dd = 0; dd < 4; dd++) {
                const int d = c * 4 + dd;
                float v = 0.f;
                #pragma unroll
                for (int j = 0; j < 4; j++)
                    v += e[i][j] * vs[(tx * 4 + j) * VS_STR + d];
                cbuf[((ty * 4 + i) * 4 + dd) * 16 + tx] = v;
            }
        }
        __syncthreads();

        if (c == 0 && t < 64) {        // rowsum reduce (once)
            float s = 0.f;
            #pragma unroll
            for (int q = 0; q < 16; q++)
                s += sbuf[t * 16 + q];
            if (m0 + t < HLEN)
                g_sump[(bc * 4 + nt) * HLEN + m0 + t] = s;
        }
        {                               // ctx reduce: 256 outputs this chunk
            const int m  = t >> 2;
            const int dd = t & 3;
            float s = 0.f;
            #pragma unroll
            for (int q = 0; q < 16; q++)
                s += cbuf[t * 16 + q];
            if (m0 + m < HLEN)
                g_ctxp[((bc * 4 + nt) * HLEN + m0 + m) * DK + c * 4 + dd] = s;
        }
        __syncthreads();
    }
}

// ---------------------------------------------------------------------------
// Kernel 3: finalize.  grid (bc=20, ht=25); warp per row.  Reads 4 partial
// rowsums -> rs, 4 partial ctx vectors -> context, and scales the E row in
// place.  Pure short streaming, ~3us.
// ---------------------------------------------------------------------------
__global__ __launch_bounds__(256) void finalize_kernel(float* __restrict__ out)
{
    const int bc   = blockIdx.x;
    const int ht   = blockIdx.y;      // 0..24
    const int t    = threadIdx.x;
    const int w    = t >> 5;          // 0..7
    const int lane = t & 31;

    const int h = ht * 8 + w;         // 0..199
    const int r = bc * HLEN + h;

    // rs (all lanes redundantly; broadcast loads)
    float s = 1e-8f;
    #pragma unroll
    for (int nt = 0; nt < 4; nt++)
        s += g_sump[(bc * 4 + nt) * HLEN + h];
    const float rs = 1.f / s;

    // context
    if (lane < DK) {
        float c = 0.f;
        #pragma unroll
        for (int nt = 0; nt < 4; nt++)
            c += g_ctxp[((bc * 4 + nt) * HLEN + h) * DK + lane];
        out[r * DK + lane] = c * rs;
    }

    // scale E row in place
    float* E = out + ATTN_OFF + (size_t)r * HLEN;
    #pragma unroll
    for (int k = 0; k < 7; k++) {
        const int n = lane + 32 * k;
        if (n < HLEN) E[n] *= rs;
    }
}

extern "C" void kernel_launch(void* const* d_in, const int* in_sizes, int n_in,
                              void* d_out, int out_size)
{
    const float* Q   = (const float*)d_in[0];
    const float* K   = (const float*)d_in[1];
    const float* V   = (const float*)d_in[2];
    const float* cdd = (const float*)d_in[3];
    const float* W   = (const float*)d_in[4];
    const float* b   = (const float*)d_in[5];
    const float* W1  = (const float*)d_in[6];
    const float* b1  = (const float*)d_in[7];

    proj_kernel<<<dim3(NROWS, 3), 200>>>(Q, K, V, cdd, W, b, W1, b1);
    score_kernel<<<dim3(BC, 4, 4), 256>>>((float*)d_out);
    finalize_kernel<<<dim3(BC, 25), 256>>>((float*)d_out);
}

// round 16
// speedup vs baseline: 2.3117x; 1.0616x over previous
#include <cuda_runtime.h>

// Problem constants
#define BC        20      // B*C
#define HLEN      200     // his_length
#define DK        20
#define NROWS     4000    // BC*HLEN
#define ROW_ELEMS 8000    // D_INNER(400) * DK(20)
#define CTX_ELEMS (NROWS*DK)        // 80000
#define ATTN_OFF  CTX_ELEMS

// Projected q,k,v,c in TRANSPOSED layout: [bc][d][h] -> (bc*20+d)*200+h
__device__ float g_qT[CTX_ELEMS];
__device__ float g_kT[CTX_ELEMS];
__device__ float g_vT[CTX_ELEMS];
__device__ float g_cT[CTX_ELEMS];

// ---------------------------------------------------------------------------
// Kernel 1: projections — exact R5 body (proven 60.3us @ 82.8% DRAM).
// grid = (row 0..3999, tensor 0..2); 200 threads.
// ---------------------------------------------------------------------------
__global__ __launch_bounds__(200) void proj_kernel(
    const float* __restrict__ Q, const float* __restrict__ K,
    const float* __restrict__ V, const float* __restrict__ cdd,
    const float* __restrict__ W, const float* __restrict__ bp,
    const float* __restrict__ W1, const float* __restrict__ b1p)
{
    __shared__ float Ws[400];
    __shared__ float4 red[200];

    const int r = blockIdx.x;      // row 0..3999
    const int a = blockIdx.y;      // tensor 0..2
    const int t = threadIdx.x;     // 0..199
    const int bc = r / HLEN;
    const int h  = r - bc * HLEN;

    Ws[t]       = W[t];
    Ws[t + 200] = W[t + 200];
    __syncthreads();

    const float bias = __ldg(bp);
    const size_t base = (size_t)r * ROW_ELEMS;

    const float* src = (a == 0) ? (Q + base) : (a == 1) ? (K + base) : (V + base);
    float*       dst = (a == 0) ? g_qT : (a == 1) ? g_kT : g_vT;

    const float4* p = (const float4*)src;
    float a0 = 0.f, a1 = 0.f, a2 = 0.f, a3 = 0.f;
    #pragma unroll
    for (int j = 0; j < 10; j++) {
        const int i4 = t + 200 * j;
        const float4 v4 = p[i4];
        const float wv = Ws[(i4 * 4) / 20];    // same n for all 4 lanes
        a0 += v4.x * wv;
        a1 += v4.y * wv;
        a2 += v4.z * wv;
        a3 += v4.w * wv;
    }
    red[t] = make_float4(a0, a1, a2, a3);
    __syncthreads();

    if (t < 20) {
        const int e  = t & 3;
        const int st = t >> 2;
        float s = bias;
        #pragma unroll 8
        for (int tp = st; tp < 200; tp += 5)
            s += ((const float*)&red[tp])[e];
        dst[(bc * DK + t) * HLEN + h] = s;
    }

    if (a == 2 && t < 20) {
        const float b1 = __ldg(b1p);
        const float* cb = cdd + (size_t)r * 400;
        float s = b1;
        #pragma unroll
        for (int n = 0; n < 20; n++)
            s += cb[n * 20 + t] * __ldg(W1 + n);
        g_cT[(bc * DK + t) * HLEN + h] = s;
    }
}

// ---------------------------------------------------------------------------
// Kernel 2: single-wave fused attention.  grid = (bc=20, mt=7) = 140 blocks;
// 256 threads = 8 warps.  Warp w owns rows m = m0+4w..4w+3; lane owns cols
// n = lane + 32*j (j<7, 224-pad).  One __syncthreads (after staging);
// everything else warp-synchronous.
//   Phase A: scores acc[4][7] (per d: 11 LDS -> 28 FMA), e in regs,
//            row sums via shfl butterfly, normalized attn STG from regs.
//   Phase B: context in two d-halves (c[4][10] regs), per (j,dd):
//            1 LDS -> 4 FMA, shfl reduce, predicated-select write.
// smem (floats): ys[40*224]=8960 @0, xs[40*32]=1280 @8960,
//                vt[20*224]=4480 @10240 -> 14720 (58.9KB dynamic)
// ---------------------------------------------------------------------------
#define NP   224
#define SMEM_FLOATS 14720
#define SMEM_BYTES  (SMEM_FLOATS * 4)

__global__ __launch_bounds__(256) void attn_one(float* __restrict__ out)
{
    extern __shared__ float sm[];
    float* ys = sm;             // [d][n] d<40, zero-padded n>=200
    float* xs = sm + 8960;      // [d][m] d<40, m<32
    float* vt = sm + 10240;     // [d][n] d<20, zero-padded

    const int bc = blockIdx.x;
    const int m0 = blockIdx.y * 32;
    const int t  = threadIdx.x;
    const int w    = t >> 5;
    const int lane = t & 31;

    // ---- stage everything once ----
    for (int i = t; i < 40 * NP; i += 256) {
        const int d = i / NP, n = i - NP * d;
        float v = 0.f;
        if (n < HLEN)
            v = (d < 20) ? g_kT[(bc * DK + d) * HLEN + n]
                         : g_cT[(bc * DK + d - 20) * HLEN + n];
        ys[i] = v;
    }
    for (int i = t; i < 20 * NP; i += 256) {
        const int d = i / NP, n = i - NP * d;
        vt[i] = (n < HLEN) ? g_vT[(bc * DK + d) * HLEN + n] : 0.f;
    }
    for (int i = t; i < 40 * 32; i += 256) {
        const int d = i >> 5, m = i & 31;
        float v = 0.f;
        if (m0 + m < HLEN)
            v = (d < 20) ? g_qT[(bc * DK + d) * HLEN + m0 + m]
                         : g_kT[(bc * DK + d - 20) * HLEN + m0 + m];
        xs[i] = v;
    }
    __syncthreads();

    // ---- Phase A: scores ----
    float acc[4][7];
    #pragma unroll
    for (int i = 0; i < 4; i++)
        #pragma unroll
        for (int j = 0; j < 7; j++)
            acc[i][j] = 0.f;

    const int mb = 4 * w;     // local row base
    #pragma unroll 4
    for (int d = 0; d < 40; d++) {
        float xa[4];
        #pragma unroll
        for (int i = 0; i < 4; i++)
            xa[i] = xs[d * 32 + mb + i];          // broadcast
        #pragma unroll
        for (int j = 0; j < 7; j++) {
            const float y = ys[d * NP + lane + 32 * j];   // stride-1
            #pragma unroll
            for (int i = 0; i < 4; i++)
                acc[i][j] += xa[i] * y;
        }
    }

    const float isd = 0.22360679774997896f;   // 1/sqrt(20)
    float e[4][7];
    float rs[4];
    #pragma unroll
    for (int i = 0; i < 4; i++) {
        float rsum = 0.f;
        #pragma unroll
        for (int j = 0; j < 7; j++) {
            const bool valid = (lane + 32 * j) < HLEN;
            e[i][j] = valid ? __expf(acc[i][j] * isd) : 0.f;
            rsum += e[i][j];
        }
        #pragma unroll
        for (int o = 16; o; o >>= 1)
            rsum += __shfl_xor_sync(0xFFFFFFFFu, rsum, o);
        rs[i] = 1.f / (rsum + 1e-8f);
    }

    // ---- normalized attn writes straight from registers ----
    #pragma unroll
    for (int i = 0; i < 4; i++) {
        const int m = m0 + mb + i;
        if (m < HLEN) {
            float* attn = out + ATTN_OFF + (size_t)(bc * HLEN + m) * HLEN;
            #pragma unroll
            for (int j = 0; j < 7; j++) {
                const int n = lane + 32 * j;
                if (n < HLEN) attn[n] = e[i][j] * rs[i];
            }
        }
    }

    // ---- Phase B: context in two d-halves (c[4][10] regs each) ----
    #pragma unroll 1
    for (int p = 0; p < 2; p++) {
        float c[4][10];
        #pragma unroll
        for (int i = 0; i < 4; i++)
            #pragma unroll
            for (int dd = 0; dd < 10; dd++)
                c[i][dd] = 0.f;

        #pragma unroll
        for (int j = 0; j < 7; j++) {
            #pragma unroll
            for (int dd = 0; dd < 10; dd++) {
                const float v = vt[(p * 10 + dd) * NP + lane + 32 * j];
                #pragma unroll
                for (int i = 0; i < 4; i++)
                    c[i][dd] += e[i][j] * v;
            }
        }

        // warp reduce + write
        #pragma unroll
        for (int dd = 0; dd < 10; dd++) {
            #pragma unroll
            for (int i = 0; i < 4; i++) {
                #pragma unroll
                for (int o = 16; o; o >>= 1)
                    c[i][dd] += __shfl_xor_sync(0xFFFFFFFFu, c[i][dd], o);
            }
        }
        #pragma unroll
        for (int i = 0; i < 4; i++) {
            float o = 0.f;
            #pragma unroll
            for (int dd = 0; dd < 10; dd++)
                if (lane == dd) o = c[i][dd];     // predicated select
            const int m = m0 + mb + i;
            if (lane < 10 && m < HLEN)
                out[(bc * HLEN + m) * DK + p * 10 + lane] = o * rs[i];
        }
    }
}

extern "C" void kernel_launch(void* const* d_in, const int* in_sizes, int n_in,
                              void* d_out, int out_size)
{
    const float* Q   = (const float*)d_in[0];
    const float* K   = (const float*)d_in[1];
    const float* V   = (const float*)d_in[2];
    const float* cdd = (const float*)d_in[3];
    const float* W   = (const float*)d_in[4];
    const float* b   = (const float*)d_in[5];
    const float* W1  = (const float*)d_in[6];
    const float* b1  = (const float*)d_in[7];

    cudaFuncSetAttribute(attn_one,
                         cudaFuncAttributeMaxDynamicSharedMemorySize, SMEM_BYTES);

    proj_kernel<<<dim3(NROWS, 3), 200>>>(Q, K, V, cdd, W, b, W1, b1);
    attn_one<<<dim3(BC, 7), 256, SMEM_BYTES>>>((float*)d_out);
}

// round 17
// speedup vs baseline: 2.3302x; 1.0080x over previous
#include <cuda_runtime.h>

// Problem constants
#define BC        20      // B*C
#define HLEN      200     // his_length
#define DK        20
#define NROWS     4000    // BC*HLEN
#define ROW_ELEMS 8000    // D_INNER(400) * DK(20)
#define CTX_ELEMS (NROWS*DK)        // 80000
#define ATTN_OFF  CTX_ELEMS

// Projected q,k,v,c in TRANSPOSED layout: [bc][d][h] -> (bc*20+d)*200+h
__device__ float g_qT[CTX_ELEMS];
__device__ float g_kT[CTX_ELEMS];
__device__ float g_vT[CTX_ELEMS];
__device__ float g_cT[CTX_ELEMS];

// ---------------------------------------------------------------------------
// Kernel 1: projections — exact R5 body (proven 60.3us @ 82.8% DRAM).
// grid = (row 0..3999, tensor 0..2); 200 threads.
// ---------------------------------------------------------------------------
__global__ __launch_bounds__(200) void proj_kernel(
    const float* __restrict__ Q, const float* __restrict__ K,
    const float* __restrict__ V, const float* __restrict__ cdd,
    const float* __restrict__ W, const float* __restrict__ bp,
    const float* __restrict__ W1, const float* __restrict__ b1p)
{
    __shared__ float Ws[400];
    __shared__ float4 red[200];

    const int r = blockIdx.x;      // row 0..3999
    const int a = blockIdx.y;      // tensor 0..2
    const int t = threadIdx.x;     // 0..199
    const int bc = r / HLEN;
    const int h  = r - bc * HLEN;

    Ws[t]       = W[t];
    Ws[t + 200] = W[t + 200];
    __syncthreads();

    const float bias = __ldg(bp);
    const size_t base = (size_t)r * ROW_ELEMS;

    const float* src = (a == 0) ? (Q + base) : (a == 1) ? (K + base) : (V + base);
    float*       dst = (a == 0) ? g_qT : (a == 1) ? g_kT : g_vT;

    const float4* p = (const float4*)src;
    float a0 = 0.f, a1 = 0.f, a2 = 0.f, a3 = 0.f;
    #pragma unroll
    for (int j = 0; j < 10; j++) {
        const int i4 = t + 200 * j;
        const float4 v4 = p[i4];
        const float wv = Ws[(i4 * 4) / 20];    // same n for all 4 lanes
        a0 += v4.x * wv;
        a1 += v4.y * wv;
        a2 += v4.z * wv;
        a3 += v4.w * wv;
    }
    red[t] = make_float4(a0, a1, a2, a3);
    __syncthreads();

    if (t < 20) {
        const int e  = t & 3;
        const int st = t >> 2;
        float s = bias;
        #pragma unroll 8
        for (int tp = st; tp < 200; tp += 5)
            s += ((const float*)&red[tp])[e];
        dst[(bc * DK + t) * HLEN + h] = s;
    }

    if (a == 2 && t < 20) {
        const float b1 = __ldg(b1p);
        const float* cb = cdd + (size_t)r * 400;
        float s = b1;
        #pragma unroll
        for (int n = 0; n < 20; n++)
            s += cb[n * 20 + t] * __ldg(W1 + n);
        g_cT[(bc * DK + t) * HLEN + h] = s;
    }
}

// ---------------------------------------------------------------------------
// Kernel 2: single-wave fused attention.  grid = (bc=20, mt=7) = 140 blocks;
// 256 threads = 8 warps.  Warp w owns rows m = m0+4w..4w+3; lane owns cols
// n = lane + 32*j (j<7, 224-pad).
// __launch_bounds__(256, 1): one wave means occupancy >1 block/SM is
// unreachable anyway — give ptxas the full register file so acc/e/c stay
// register-resident (R16 spilled at regs=64 and ran 32us).
// smem (floats): ys[40*224]=8960 @0, xs[40*32]=1280 @8960,
//                vt[20*224]=4480 @10240 -> 14720 (58.9KB dynamic)
// ---------------------------------------------------------------------------
#define NP   224
#define SMEM_FLOATS 14720
#define SMEM_BYTES  (SMEM_FLOATS * 4)

__global__ __launch_bounds__(256, 1) void attn_one(float* __restrict__ out)
{
    extern __shared__ float sm[];
    float* ys = sm;             // [d][n] d<40, zero-padded n>=200
    float* xs = sm + 8960;      // [d][m] d<40, m<32
    float* vt = sm + 10240;     // [d][n] d<20, zero-padded

    const int bc = blockIdx.x;
    const int m0 = blockIdx.y * 32;
    const int t  = threadIdx.x;
    const int w    = t >> 5;
    const int lane = t & 31;

    // ---- stage everything once ----
    for (int i = t; i < 40 * NP; i += 256) {
        const int d = i / NP, n = i - NP * d;
        float v = 0.f;
        if (n < HLEN)
            v = (d < 20) ? g_kT[(bc * DK + d) * HLEN + n]
                         : g_cT[(bc * DK + d - 20) * HLEN + n];
        ys[i] = v;
    }
    for (int i = t; i < 20 * NP; i += 256) {
        const int d = i / NP, n = i - NP * d;
        vt[i] = (n < HLEN) ? g_vT[(bc * DK + d) * HLEN + n] : 0.f;
    }
    for (int i = t; i < 40 * 32; i += 256) {
        const int d = i >> 5, m = i & 31;
        float v = 0.f;
        if (m0 + m < HLEN)
            v = (d < 20) ? g_qT[(bc * DK + d) * HLEN + m0 + m]
                         : g_kT[(bc * DK + d - 20) * HLEN + m0 + m];
        xs[i] = v;
    }
    __syncthreads();

    // ---- Phase A: scores ----
    float acc[4][7];
    #pragma unroll
    for (int i = 0; i < 4; i++)
        #pragma unroll
        for (int j = 0; j < 7; j++)
            acc[i][j] = 0.f;

    const int mb = 4 * w;     // local row base
    #pragma unroll 4
    for (int d = 0; d < 40; d++) {
        float xa[4];
        #pragma unroll
        for (int i = 0; i < 4; i++)
            xa[i] = xs[d * 32 + mb + i];          // broadcast
        #pragma unroll
        for (int j = 0; j < 7; j++) {
            const float y = ys[d * NP + lane + 32 * j];   // stride-1
            #pragma unroll
            for (int i = 0; i < 4; i++)
                acc[i][j] += xa[i] * y;
        }
    }

    const float isd = 0.22360679774997896f;   // 1/sqrt(20)
    float e[4][7];
    float rs[4];
    #pragma unroll
    for (int i = 0; i < 4; i++) {
        float rsum = 0.f;
        #pragma unroll
        for (int j = 0; j < 7; j++) {
            const bool valid = (lane + 32 * j) < HLEN;
            e[i][j] = valid ? __expf(acc[i][j] * isd) : 0.f;
            rsum += e[i][j];
        }
        #pragma unroll
        for (int o = 16; o; o >>= 1)
            rsum += __shfl_xor_sync(0xFFFFFFFFu, rsum, o);
        rs[i] = 1.f / (rsum + 1e-8f);
    }

    // ---- normalized attn writes straight from registers ----
    #pragma unroll
    for (int i = 0; i < 4; i++) {
        const int m = m0 + mb + i;
        if (m < HLEN) {
            float* attn = out + ATTN_OFF + (size_t)(bc * HLEN + m) * HLEN;
            #pragma unroll
            for (int j = 0; j < 7; j++) {
                const int n = lane + 32 * j;
                if (n < HLEN) attn[n] = e[i][j] * rs[i];
            }
        }
    }

    // ---- Phase B: context in two d-halves (c[4][10] regs each) ----
    #pragma unroll 1
    for (int p = 0; p < 2; p++) {
        float c[4][10];
        #pragma unroll
        for (int i = 0; i < 4; i++)
            #pragma unroll
            for (int dd = 0; dd < 10; dd++)
                c[i][dd] = 0.f;

        #pragma unroll
        for (int j = 0; j < 7; j++) {
            #pragma unroll
            for (int dd = 0; dd < 10; dd++) {
                const float v = vt[(p * 10 + dd) * NP + lane + 32 * j];
                #pragma unroll
                for (int i = 0; i < 4; i++)
                    c[i][dd] += e[i][j] * v;
            }
        }

        // warp reduce + write
        #pragma unroll
        for (int dd = 0; dd < 10; dd++) {
            #pragma unroll
            for (int i = 0; i < 4; i++) {
                #pragma unroll
                for (int o = 16; o; o >>= 1)
                    c[i][dd] += __shfl_xor_sync(0xFFFFFFFFu, c[i][dd], o);
            }
        }
        #pragma unroll
        for (int i = 0; i < 4; i++) {
            float o = 0.f;
            #pragma unroll
            for (int dd = 0; dd < 10; dd++)
                if (lane == dd) o = c[i][dd];     // predicated select
            const int m = m0 + mb + i;
            if (lane < 10 && m < HLEN)
                out[(bc * HLEN + m) * DK + p * 10 + lane] = o * rs[i];
        }
    }
}

extern "C" void kernel_launch(void* const* d_in, const int* in_sizes, int n_in,
                              void* d_out, int out_size)
{
    const float* Q   = (const float*)d_in[0];
    const float* K   = (const float*)d_in[1];
    const float* V   = (const float*)d_in[2];
    const float* cdd = (const float*)d_in[3];
    const float* W   = (const float*)d_in[4];
    const float* b   = (const float*)d_in[5];
    const float* W1  = (const float*)d_in[6];
    const float* b1  = (const float*)d_in[7];

    cudaFuncSetAttribute(attn_one,
                         cudaFuncAttributeMaxDynamicSharedMemorySize, SMEM_BYTES);

    proj_kernel<<<dim3(NROWS, 3), 200>>>(Q, K, V, cdd, W, b, W1, b1);
    attn_one<<<dim3(BC, 7), 256, SMEM_BYTES>>>((float*)d_out);
}